// round 15
// baseline (speedup 1.0000x reference)
#include <cuda_runtime.h>
#include <cuda_fp16.h>
#include <math.h>

#define T_DIM 512
#define B_DIM 1024
#define V_DIM 96
#define L_DIM 48
#define PKW   52          // packed row: 48 label probs + blank + zero pad (104 B fp16)
#define CHUNK 4           // timesteps per cp.async chunk (416 B contiguous)
#define NCH   4           // ring depth (chunks)
#define NCHUNKS (T_DIM / CHUNK)   // 128
#define PSCALE_LOG2 5     // stored prob = p * 2^5 (keeps fp16 out of subnormals)
#define SROW  104         // G smem row stride (floats)

#define B_BLOCKS 128      // forward-role blocks (8 warps = 8 batch elems each) -- FIRST
#define G_BLOCKS 16384    // gather-role blocks (8 warps x 4 rows = 32 rows each)
#define SLICES   32       // t-slices of 16 timesteps; 512 G blocks per slice
#define SLICE_GBLOCKS 512

// scratch (no cudaMalloc allowed); device globals zero-initialized at load,
// self-reset by the last forward warp each run.
__device__ __align__(16) __half g_pk[(size_t)B_DIM * T_DIM * PKW];   // ~52 MB
__device__ unsigned long long g_acc;       // fixed-point loss sum
__device__ int g_cnt;                      // finished-warp counter
__device__ int g_done[SLICES];             // per-slice G-block completion counts

// ---------------------------------------------------------------------------
// Fused single-launch producer/consumer kernel.
//   blocks [0, B_BLOCKS): forward role -- resident from wave 1, warp-per-batch
//     CTC recursion; spins on g_done before each cp.async chunk; fused
//     deterministic mean via fixed-point atomic; self-resets globals.
//   blocks [B_BLOCKS, +G_BLOCKS): gather role -- logsumexp+gather+normalize,
//     publishes t-slice completion via fence + atomic counter.
// smem union is 13.3 KB (same as the standalone G kernel) so G keeps its
// occupancy and L1 carveout; B-first ordering gives real overlap.
// ---------------------------------------------------------------------------
__global__ void __launch_bounds__(256) ctc_fused(const float* __restrict__ y_pred,
                                                 const int*   __restrict__ y_true,
                                                 float* __restrict__ out) {
    __shared__ __align__(16) char smem_raw[13312];   // union: G 13.3KB / B 13.3KB
    const int bid = blockIdx.x;

    if (bid >= B_BLOCKS) {
        // =================== gather role ===================
        float* sex = (float*)smem_raw;               // [8 warps][4 * SROW]
        const int gbid = bid - B_BLOCKS;
        int wib  = threadIdx.x >> 5;
        int lane = threadIdx.x & 31;
        int g   = lane >> 3, sub = lane & 7;
        int r   = (gbid * 8 + wib) * 4 + g;          // row id = t*B + b
        int t   = r >> 10;
        int b   = r & (B_DIM - 1);

        const float* row = y_pred + (size_t)r * V_DIM;
        const float4* rp = (const float4*)row + sub;
        float4 v0 = rp[0];
        float4 v1 = rp[8];
        float4 v2 = rp[16];

        float m = fmaxf(fmaxf(fmaxf(v0.x, v0.y), fmaxf(v0.z, v0.w)),
                 fmaxf(fmaxf(fmaxf(v1.x, v1.y), fmaxf(v1.z, v1.w)),
                       fmaxf(fmaxf(v2.x, v2.y), fmaxf(v2.z, v2.w))));
        #pragma unroll
        for (int o = 4; o; o >>= 1) m = fmaxf(m, __shfl_xor_sync(0xFFFFFFFFu, m, o));

        float4 e0 = make_float4(__expf(v0.x-m), __expf(v0.y-m), __expf(v0.z-m), __expf(v0.w-m));
        float4 e1 = make_float4(__expf(v1.x-m), __expf(v1.y-m), __expf(v1.z-m), __expf(v1.w-m));
        float4 e2 = make_float4(__expf(v2.x-m), __expf(v2.y-m), __expf(v2.z-m), __expf(v2.w-m));

        float s = (e0.x+e0.y+e0.z+e0.w) + (e1.x+e1.y+e1.z+e1.w) + (e2.x+e2.y+e2.z+e2.w);
        #pragma unroll
        for (int o = 4; o; o >>= 1) s += __shfl_xor_sync(0xFFFFFFFFu, s, o);
        float inv = __fdividef((float)(1 << PSCALE_LOG2), s);   // 2^5 / sum

        float* myrow = sex + (wib * 4 + g) * SROW;
        *(float4*)(myrow + 4*sub)      = e0;
        *(float4*)(myrow + 32 + 4*sub) = e1;
        *(float4*)(myrow + 64 + 4*sub) = e2;
        __syncwarp();

        const int* lbase = y_true + b * L_DIM + 6 * sub;
        int2 la = *(const int2*)(lbase);
        int2 lb = *(const int2*)(lbase + 2);
        int2 lc = *(const int2*)(lbase + 4);

        float p0 = myrow[la.x] * inv;
        float p1 = myrow[la.y] * inv;
        float p2 = myrow[lb.x] * inv;
        float p3 = myrow[lb.y] * inv;
        float p4 = myrow[lc.x] * inv;
        float p5 = myrow[lc.y] * inv;

        __half* o_ = g_pk + ((size_t)b * T_DIM + t) * PKW + 6 * sub;
        *(__half2*)(o_)     = __float22half2_rn(make_float2(p0, p1));
        *(__half2*)(o_ + 2) = __float22half2_rn(make_float2(p2, p3));
        *(__half2*)(o_ + 4) = __float22half2_rn(make_float2(p4, p5));
        if (sub == 0) {
            *(__half2*)(o_ + 48) = __floats2half2_rn(myrow[0] * inv, 0.0f); // blank + pad
            *(__half2*)(o_ + 50) = __float2half2_rn(0.0f);                  // pad zeros
        }

        // publish: all stores visible, then count this block into its slice
        __threadfence();
        __syncthreads();
        if (threadIdx.x == 0) atomicAdd(&g_done[gbid >> 9], 1);
        return;
    }

    // =================== forward role ===================
    __half* ring = (__half*)smem_raw;   // [8 warps][NCH][CHUNK*PKW]
    const int wib = threadIdx.x >> 5;
    const int b   = bid * 8 + wib;
    const int l   = threadIdx.x & 31;

    int lab0 = 0, lab1 = 0;
    if (l < 24) {
        int2 lp = *(const int2*)(y_true + b * L_DIM + 2 * l);
        lab0 = lp.x; lab1 = lp.y;
    }
    int prevlab1 = __shfl_up_sync(0xFFFFFFFFu, lab1, 1);
    const float skip1 = (l >= 1 && l < 24 && lab0 != prevlab1) ? 1.0f : 0.0f;
    const float skip3 = (l < 24 && lab1 != lab0) ? 1.0f : 0.0f;
    // inactive lanes read probs from the zero pad -> their alphas stay 0
    const int off2 = (l < 24) ? 2 * l : 50;

    const __half* src = g_pk + (size_t)b * T_DIM * PKW;
    __half* myring = ring + wib * (NCH * CHUNK * PKW);

    #define WAIT_SLICE(s_)                                                     \
    {                                                                          \
        if (l == 0) {                                                          \
            while (*(volatile int*)&g_done[(s_)] < SLICE_GBLOCKS)              \
                __nanosleep(128);                                              \
        }                                                                      \
        __syncwarp();                                                          \
        __threadfence();                                                       \
    }

    #define ISSUE(c_)                                                          \
    {                                                                          \
        const __half* gsrc = src + (size_t)(c_) * (CHUNK * PKW);               \
        __half* sdst = myring + ((c_) & (NCH - 1)) * (CHUNK * PKW);            \
        if (l < (CHUNK * PKW) / 8) {                                           \
            unsigned sa = (unsigned)__cvta_generic_to_shared(sdst + 8 * l);    \
            asm volatile("cp.async.ca.shared.global [%0], [%1], 16;"           \
                         :: "r"(sa), "l"(gsrc + 8 * l));                       \
        }                                                                      \
        asm volatile("cp.async.commit_group;" ::: "memory");                   \
    }

    // prologue: chunks 0..2 cover t<12, all in slice 0
    WAIT_SLICE(0);
    ISSUE(0); ISSUE(1); ISSUE(2);

    float a0 = 0.0f, a1 = 0.0f, a2 = 0.0f, a3 = 0.0f;
    int acc_k = 0;   // power-of-2 shift: stored = true * 2^{acc_k + 5*steps}
    int rs = 0;      // rescale phase counter

    #define STEP(p01f, pb)                                                     \
    {                                                                          \
        float sh3 = __shfl_up_sync(0xFFFFFFFFu, a3, 1);                        \
        if (l == 0) sh3 = 0.0f;                                                \
        float n0 = (a0 + sh3) * (pb);                                          \
        float n1 = fmaf(skip1, sh3, a0 + a1) * (p01f).x;                       \
        float n2 = (a1 + a2) * (pb);                                           \
        float n3 = fmaf(skip3, a1, a2 + a3) * (p01f).y;                        \
        a0 = n0; a1 = n1; a2 = n2; a3 = n3;                                    \
        if ((++rs & 3) == 0) {                                                 \
            float v = fmaxf(fmaxf(a0, a1), fmaxf(a2, a3));                     \
            unsigned mb = __reduce_max_sync(0xFFFFFFFFu, __float_as_uint(v));  \
            int eb = (int)(mb >> 23);                                          \
            int shift = (127 + 110) - eb;       /* recenter max at 2^110 */    \
            if (shift >  126) shift =  126;                                    \
            if (shift < -126) shift = -126;                                    \
            float scale = __int_as_float((127 + shift) << 23);                 \
            a0 *= scale; a1 *= scale; a2 *= scale; a3 *= scale;                \
            acc_k += shift;                                                    \
        }                                                                      \
    }

    for (int c = 0; c < NCHUNKS; c++) {
        int n = NCHUNKS - 1 - c; if (n > NCH - 2) n = NCH - 2;
        if      (n == 2) asm volatile("cp.async.wait_group 2;" ::: "memory");
        else if (n == 1) asm volatile("cp.async.wait_group 1;" ::: "memory");
        else             asm volatile("cp.async.wait_group 0;" ::: "memory");
        __syncwarp();
        if (c + NCH - 1 < NCHUNKS) {
            WAIT_SLICE((CHUNK * (c + NCH - 1) + CHUNK - 1) >> 4);
            ISSUE(c + NCH - 1);
        }

        const __half* pk = myring + (c & (NCH - 1)) * (CHUNK * PKW);
        #pragma unroll
        for (int j = 0; j < CHUNK; j++) {
            const __half* prow = pk + j * PKW;
            float2 p01 = __half22float2(*(const __half2*)(prow + off2));
            float  pb  = __half2float(prow[48]);
            if (c == 0 && j == 0) {   // t = 0 init: states 0,1 on lane 0
                if (l == 0) { a0 = pb; a1 = p01.x; }
                continue;
            }
            STEP(p01, pb);
        }
        __syncwarp();   // all lanes done reading slot before it is re-issued
    }
    #undef STEP
    #undef ISSUE
    #undef WAIT_SLICE

    // terminal states: s=95 (lane 23, a3) and s=96 (lane 24, a0)
    float v95 = __shfl_sync(0xFFFFFFFFu, a3, 23);
    float v96 = __shfl_sync(0xFFFFFFFFu, a0, 24);
    if (l == 0) {
        double kk = (double)acc_k + (double)(PSCALE_LOG2 * T_DIM);
        double loss = -log((double)(v95 + v96)) + kk * 0.6931471805599453094;
        // deterministic fused mean: fixed-point (2^32) integer accumulate
        unsigned long long fx = (unsigned long long)(loss * 4294967296.0 + 0.5);
        atomicAdd(&g_acc, fx);
        __threadfence();
        int done = atomicAdd(&g_cnt, 1);
        if (done == B_DIM - 1) {
            unsigned long long tot = atomicAdd(&g_acc, 0ull);
            out[0] = (float)((double)tot * (1.0 / 4294967296.0 / (double)B_DIM));
            // self-reset for the next replay (all producers & consumers done)
            g_acc = 0ull;
            g_cnt = 0;
            #pragma unroll
            for (int s2 = 0; s2 < SLICES; s2++) g_done[s2] = 0;
            __threadfence();
        }
    }
}

extern "C" void kernel_launch(void* const* d_in, const int* in_sizes, int n_in,
                              void* d_out, int out_size) {
    const int*   y_true;
    const float* y_pred;
    if (in_sizes[0] == B_DIM * L_DIM) {
        y_true = (const int*)d_in[0];
        y_pred = (const float*)d_in[1];
    } else {
        y_true = (const int*)d_in[1];
        y_pred = (const float*)d_in[0];
    }

    // single fused launch: 128 forward blocks FIRST, then 16384 gather blocks
    ctc_fused<<<B_BLOCKS + G_BLOCKS, 256>>>(y_pred, y_true, (float*)d_out);
}

// round 16
// speedup vs baseline: 5.1176x; 5.1176x over previous
#include <cuda_runtime.h>
#include <cuda_fp16.h>
#include <math.h>

#define T_DIM 512
#define B_DIM 1024
#define V_DIM 96
#define L_DIM 48
#define PKW   52          // packed row: 48 label probs + blank + zero pad (104 B fp16)
#define CHUNK 16          // timesteps per cp.async chunk (1664 B contiguous)
#define NCH   4           // ring depth (chunks)
#define NCHUNKS (T_DIM / CHUNK)   // 32
#define PSCALE_LOG2 5     // stored prob = p * 2^5 (keeps fp16 out of subnormals)
#define SROW  104         // G smem row stride (floats)

// scratch (no cudaMalloc allowed)
__device__ __align__(16) __half g_pk[(size_t)B_DIM * T_DIM * PKW];   // ~52 MB
__device__ unsigned long long g_acc;      // fixed-point loss sum (zeroed by G)
__device__ int g_cnt = 0;                 // completion counter (self-resetting)

// ---------------------------------------------------------------------------
// Kernel G: fused logsumexp + gather + normalize -- 4 rows per warp, fp16 out.
// Row r = t*B+b handled by an 8-lane subgroup (sub = lane&7). The 12 exps per
// lane are staged in SMEM (3x STS.128) so the 49 gathers are LDS hits.
// Writes zeros at pad offsets 49-51 (kernel B's inactive lanes read the pad).
// Zeroes the loss accumulator for kernel B (strictly ordered in-stream).
// ---------------------------------------------------------------------------
__global__ void __launch_bounds__(256) gather_kernel(const float* __restrict__ y_pred,
                                                     const int*   __restrict__ y_true) {
    __shared__ float sex[8][4 * SROW];    // 8 warps x 4 rows x 104 floats = 13.3 KB

    if (blockIdx.x == 0 && threadIdx.x == 0) g_acc = 0ull;   // reset for B

    int wib  = threadIdx.x >> 5;
    int warp = (blockIdx.x * blockDim.x + threadIdx.x) >> 5;
    int lane = threadIdx.x & 31;
    int g   = lane >> 3, sub = lane & 7;
    int r   = warp * 4 + g;              // grid sized exactly: 4 rows per warp
    int t   = r >> 10;                   // r / B_DIM
    int b   = r & (B_DIM - 1);

    const float* row = y_pred + (size_t)r * V_DIM;
    const float4* rp = (const float4*)row + sub;
    float4 v0 = rp[0];      // elems  4*sub    .. 4*sub+3
    float4 v1 = rp[8];      // elems 32+4*sub  ..
    float4 v2 = rp[16];     // elems 64+4*sub  ..

    float m = fmaxf(fmaxf(fmaxf(v0.x, v0.y), fmaxf(v0.z, v0.w)),
             fmaxf(fmaxf(fmaxf(v1.x, v1.y), fmaxf(v1.z, v1.w)),
                   fmaxf(fmaxf(v2.x, v2.y), fmaxf(v2.z, v2.w))));
    #pragma unroll
    for (int o = 4; o; o >>= 1) m = fmaxf(m, __shfl_xor_sync(0xFFFFFFFFu, m, o));

    float4 e0 = make_float4(__expf(v0.x-m), __expf(v0.y-m), __expf(v0.z-m), __expf(v0.w-m));
    float4 e1 = make_float4(__expf(v1.x-m), __expf(v1.y-m), __expf(v1.z-m), __expf(v1.w-m));
    float4 e2 = make_float4(__expf(v2.x-m), __expf(v2.y-m), __expf(v2.z-m), __expf(v2.w-m));

    float s = (e0.x+e0.y+e0.z+e0.w) + (e1.x+e1.y+e1.z+e1.w) + (e2.x+e2.y+e2.z+e2.w);
    #pragma unroll
    for (int o = 4; o; o >>= 1) s += __shfl_xor_sync(0xFFFFFFFFu, s, o);
    float inv = __fdividef((float)(1 << PSCALE_LOG2), s);   // 2^5 / sum

    float* myrow = &sex[wib][g * SROW];
    *(float4*)(myrow + 4*sub)      = e0;
    *(float4*)(myrow + 32 + 4*sub) = e1;
    *(float4*)(myrow + 64 + 4*sub) = e2;
    __syncwarp();

    const int* lbase = y_true + b * L_DIM + 6 * sub;
    int2 la = *(const int2*)(lbase);
    int2 lb = *(const int2*)(lbase + 2);
    int2 lc = *(const int2*)(lbase + 4);

    float p0 = myrow[la.x] * inv;
    float p1 = myrow[la.y] * inv;
    float p2 = myrow[lb.x] * inv;
    float p3 = myrow[lb.y] * inv;
    float p4 = myrow[lc.x] * inv;
    float p5 = myrow[lc.y] * inv;

    __half* out = g_pk + ((size_t)b * T_DIM + t) * PKW + 6 * sub;
    *(__half2*)(out)     = __float22half2_rn(make_float2(p0, p1));
    *(__half2*)(out + 2) = __float22half2_rn(make_float2(p2, p3));
    *(__half2*)(out + 4) = __float22half2_rn(make_float2(p4, p5));
    if (sub == 0) {
        *(__half2*)(out + 48) = __floats2half2_rn(myrow[0] * inv, 0.0f); // blank + pad
        *(__half2*)(out + 50) = __float2half2_rn(0.0f);                  // pad zeros
    }
}

// ---------------------------------------------------------------------------
// Kernel B: CTC forward recursion, warp per batch element, ALL-FP32 alphas.
// Lane l owns states 4l..4l+3; one __shfl_up per step. No lane masks:
// inactive lanes read probs from the zero pad so their alphas stay 0.
// Range: exact power-of-2 rescale every 4 steps via REDUX.SYNC, recenter 2^110.
// fp16 probs via cp.async smem ring; each chunk's 16 steps of probs are
// preloaded into registers at chunk start (LDS off the serial chain).
// Mean fused: fixed-point (x 2^32) integer atomic -> bit-deterministic;
// last-finishing warp writes d_out and self-resets g_cnt.
// ---------------------------------------------------------------------------
#define NWARP 2   // warps (batch elements) per block
__global__ void __launch_bounds__(64) ctc_forward(const int* __restrict__ y_true,
                                                  float* __restrict__ out) {
    __shared__ __align__(16) __half ring[NWARP][NCH][CHUNK * PKW];  // 13.3 KB

    const int wib = threadIdx.x >> 5;
    const int b   = blockIdx.x * NWARP + wib;
    const int l   = threadIdx.x & 31;

    // skip-transition predicates
    int lab0 = 0, lab1 = 0;
    if (l < 24) {
        int2 lp = *(const int2*)(y_true + b * L_DIM + 2 * l);
        lab0 = lp.x; lab1 = lp.y;
    }
    int prevlab1 = __shfl_up_sync(0xFFFFFFFFu, lab1, 1);
    const float skip1 = (l >= 1 && l < 24 && lab0 != prevlab1) ? 1.0f : 0.0f;
    const float skip3 = (l < 24 && lab1 != lab0) ? 1.0f : 0.0f;
    // inactive lanes read probs from the zero pad -> their alphas stay 0
    const int off2 = (l < 24) ? 2 * l : 50;

    const __half* src = g_pk + (size_t)b * T_DIM * PKW;

    // issue one chunk copy: 104 x 16B cp.async, one commit_group
    #define ISSUE(c_)                                                          \
    {                                                                          \
        const __half* gsrc = src + (size_t)(c_) * (CHUNK * PKW);               \
        __half* sdst = &ring[wib][(c_) & (NCH - 1)][0];                        \
        for (int i = l; i < (CHUNK * PKW) / 8; i += 32) {                      \
            unsigned sa = (unsigned)__cvta_generic_to_shared(sdst + 8 * i);    \
            asm volatile("cp.async.ca.shared.global [%0], [%1], 16;"           \
                         :: "r"(sa), "l"(gsrc + 8 * i));                       \
        }                                                                      \
        asm volatile("cp.async.commit_group;" ::: "memory");                   \
    }

    // prologue: chunks 0..NCH-2 in flight
    ISSUE(0); ISSUE(1); ISSUE(2);

    float a0 = 0.0f, a1 = 0.0f, a2 = 0.0f, a3 = 0.0f;
    int acc_k = 0;   // power-of-2 shift: stored = true * 2^{acc_k + 5*steps}

    #define STEP(j, p01f, pb)                                                  \
    {                                                                          \
        float sh3 = __shfl_up_sync(0xFFFFFFFFu, a3, 1);                        \
        if (l == 0) sh3 = 0.0f;                                                \
        float n0 = (a0 + sh3) * (pb);                                          \
        float n1 = fmaf(skip1, sh3, a0 + a1) * (p01f).x;                       \
        float n2 = (a1 + a2) * (pb);                                           \
        float n3 = fmaf(skip3, a1, a2 + a3) * (p01f).y;                        \
        a0 = n0; a1 = n1; a2 = n2; a3 = n3;                                    \
        if (((j) & 3) == 3) {                                                  \
            float v = fmaxf(fmaxf(a0, a1), fmaxf(a2, a3));                     \
            unsigned mb = __reduce_max_sync(0xFFFFFFFFu, __float_as_uint(v));  \
            int eb = (int)(mb >> 23);                                          \
            int shift = (127 + 110) - eb;       /* recenter max at 2^110 */    \
            if (shift >  126) shift =  126;                                    \
            if (shift < -126) shift = -126;                                    \
            float scale = __int_as_float((127 + shift) << 23);                 \
            a0 *= scale; a1 *= scale; a2 *= scale; a3 *= scale;                \
            acc_k += shift;                                                    \
        }                                                                      \
    }

    for (int c = 0; c < NCHUNKS; c++) {
        // wait until chunk c's group has completed (groups retire in order)
        int n = NCHUNKS - 1 - c; if (n > NCH - 2) n = NCH - 2;
        if      (n == 2) asm volatile("cp.async.wait_group 2;" ::: "memory");
        else if (n == 1) asm volatile("cp.async.wait_group 1;" ::: "memory");
        else             asm volatile("cp.async.wait_group 0;" ::: "memory");
        __syncwarp();

        // preload the whole chunk's probs into registers (LDS off the chain)
        const __half* pk = &ring[wib][c & (NCH - 1)][0];
        __half2 ph[CHUNK];
        __half  pbh[CHUNK];
        #pragma unroll
        for (int j = 0; j < CHUNK; j++) {
            ph[j]  = *(const __half2*)(pk + j * PKW + off2);
            pbh[j] = pk[j * PKW + 48];
        }
        __syncwarp();
        // refill the slot that will be consumed NCH-1 chunks from now
        // (writes slot (c+3)&3, never the slot just preloaded, (c)&3)
        if (c + NCH - 1 < NCHUNKS) ISSUE(c + NCH - 1);

        #pragma unroll
        for (int j = 0; j < CHUNK; j++) {
            float2 p01 = __half22float2(ph[j]);
            float  pb  = __half2float(pbh[j]);
            if (c == 0 && j == 0) {   // t = 0 init: states 0,1 on lane 0
                if (l == 0) { a0 = pb; a1 = p01.x; }
                continue;
            }
            STEP(j, p01, pb);
        }
    }
    #undef STEP
    #undef ISSUE

    // terminal states: s=95 (lane 23, a3) and s=96 (lane 24, a0)
    float v95 = __shfl_sync(0xFFFFFFFFu, a3, 23);
    float v96 = __shfl_sync(0xFFFFFFFFu, a0, 24);
    if (l == 0) {
        // stored = true * 2^{acc_k + 5*512}  (512 prob factors incl. t=0 init)
        double kk = (double)acc_k + (double)(PSCALE_LOG2 * T_DIM);
        double loss = -log((double)(v95 + v96)) + kk * 0.6931471805599453094;
        // deterministic fused mean: fixed-point (2^32) integer accumulate
        unsigned long long fx = (unsigned long long)(loss * 4294967296.0 + 0.5);
        atomicAdd(&g_acc, fx);
        __threadfence();
        int done = atomicAdd(&g_cnt, 1);
        if (done == B_DIM - 1) {
            g_cnt = 0;   // self-reset for next replay
            unsigned long long tot = atomicAdd(&g_acc, 0ull);
            out[0] = (float)((double)tot * (1.0 / 4294967296.0 / (double)B_DIM));
        }
    }
}

extern "C" void kernel_launch(void* const* d_in, const int* in_sizes, int n_in,
                              void* d_out, int out_size) {
    const int*   y_true;
    const float* y_pred;
    if (in_sizes[0] == B_DIM * L_DIM) {
        y_true = (const int*)d_in[0];
        y_pred = (const float*)d_in[1];
    } else {
        y_true = (const int*)d_in[1];
        y_pred = (const float*)d_in[0];
    }

    // G: fused logsumexp + gather + normalize (fp16 out), smem-staged gathers.
    gather_kernel<<<(T_DIM * B_DIM / 4) / 8, 256>>>(y_pred, y_true);
    // B: forward recursion + fused deterministic mean -> d_out
    ctc_forward<<<B_DIM / NWARP, 64>>>(y_true, (float*)d_out);
}

// round 17
// speedup vs baseline: 5.2564x; 1.0271x over previous
#include <cuda_runtime.h>
#include <cuda_fp16.h>
#include <math.h>

#define T_DIM 512
#define B_DIM 1024
#define V_DIM 96
#define L_DIM 48
#define PKW   52          // packed row: 48 label probs + blank + zero pad (104 B fp16)
#define CHUNK 16          // timesteps per cp.async chunk (1664 B contiguous)
#define NCH   4           // ring depth (chunks)
#define NCHUNKS (T_DIM / CHUNK)   // 32
#define PSCALE_LOG2 5     // stored prob = p * 2^5 (keeps fp16 out of subnormals)
#define SROW  104         // G smem row stride (floats)
#define RECENTER 80       // rescale target exponent (2^80)

// scratch (no cudaMalloc allowed)
__device__ __align__(16) __half g_pk[(size_t)B_DIM * T_DIM * PKW];   // ~52 MB
__device__ unsigned long long g_acc;      // fixed-point loss sum (zeroed by G)
__device__ int g_cnt = 0;                 // completion counter (self-resetting)

// ---------------------------------------------------------------------------
// Kernel G: fused logsumexp + gather + normalize -- 4 rows per warp, fp16 out.
// (unchanged from the 80 µs baseline: proven at ~46 µs)
// ---------------------------------------------------------------------------
__global__ void __launch_bounds__(256) gather_kernel(const float* __restrict__ y_pred,
                                                     const int*   __restrict__ y_true) {
    __shared__ float sex[8][4 * SROW];    // 8 warps x 4 rows x 104 floats = 13.3 KB

    if (blockIdx.x == 0 && threadIdx.x == 0) g_acc = 0ull;   // reset for B

    int wib  = threadIdx.x >> 5;
    int warp = (blockIdx.x * blockDim.x + threadIdx.x) >> 5;
    int lane = threadIdx.x & 31;
    int g   = lane >> 3, sub = lane & 7;
    int r   = warp * 4 + g;              // grid sized exactly: 4 rows per warp
    int t   = r >> 10;                   // r / B_DIM
    int b   = r & (B_DIM - 1);

    const float* row = y_pred + (size_t)r * V_DIM;
    const float4* rp = (const float4*)row + sub;
    float4 v0 = rp[0];
    float4 v1 = rp[8];
    float4 v2 = rp[16];

    float m = fmaxf(fmaxf(fmaxf(v0.x, v0.y), fmaxf(v0.z, v0.w)),
             fmaxf(fmaxf(fmaxf(v1.x, v1.y), fmaxf(v1.z, v1.w)),
                   fmaxf(fmaxf(v2.x, v2.y), fmaxf(v2.z, v2.w))));
    #pragma unroll
    for (int o = 4; o; o >>= 1) m = fmaxf(m, __shfl_xor_sync(0xFFFFFFFFu, m, o));

    float4 e0 = make_float4(__expf(v0.x-m), __expf(v0.y-m), __expf(v0.z-m), __expf(v0.w-m));
    float4 e1 = make_float4(__expf(v1.x-m), __expf(v1.y-m), __expf(v1.z-m), __expf(v1.w-m));
    float4 e2 = make_float4(__expf(v2.x-m), __expf(v2.y-m), __expf(v2.z-m), __expf(v2.w-m));

    float s = (e0.x+e0.y+e0.z+e0.w) + (e1.x+e1.y+e1.z+e1.w) + (e2.x+e2.y+e2.z+e2.w);
    #pragma unroll
    for (int o = 4; o; o >>= 1) s += __shfl_xor_sync(0xFFFFFFFFu, s, o);
    float inv = __fdividef((float)(1 << PSCALE_LOG2), s);   // 2^5 / sum

    float* myrow = &sex[wib][g * SROW];
    *(float4*)(myrow + 4*sub)      = e0;
    *(float4*)(myrow + 32 + 4*sub) = e1;
    *(float4*)(myrow + 64 + 4*sub) = e2;
    __syncwarp();

    const int* lbase = y_true + b * L_DIM + 6 * sub;
    int2 la = *(const int2*)(lbase);
    int2 lb = *(const int2*)(lbase + 2);
    int2 lc = *(const int2*)(lbase + 4);

    float p0 = myrow[la.x] * inv;
    float p1 = myrow[la.y] * inv;
    float p2 = myrow[lb.x] * inv;
    float p3 = myrow[lb.y] * inv;
    float p4 = myrow[lc.x] * inv;
    float p5 = myrow[lc.y] * inv;

    __half* out = g_pk + ((size_t)b * T_DIM + t) * PKW + 6 * sub;
    *(__half2*)(out)     = __float22half2_rn(make_float2(p0, p1));
    *(__half2*)(out + 2) = __float22half2_rn(make_float2(p2, p3));
    *(__half2*)(out + 4) = __float22half2_rn(make_float2(p4, p5));
    if (sub == 0) {
        *(__half2*)(out + 48) = __floats2half2_rn(myrow[0] * inv, 0.0f); // blank + pad
        *(__half2*)(out + 50) = __float2half2_rn(0.0f);                  // pad zeros
    }
}

// ---------------------------------------------------------------------------
// Kernel B: CTC forward recursion, warp per batch element, ALL-FP32 alphas.
// Lane l owns states 4l..4l+3; one __shfl_up per step; no lane masks
// (inactive lanes read the zero pad so their alphas stay 0 inductively).
// STALE-MAX RESCALE: at each 4-step boundary, apply the power-of-2 shift
// computed at the PREVIOUS boundary, then issue fmax+REDUX whose result is
// consumed 4 steps later -- the warp-collective REDUX latency overlaps the
// recursion instead of serializing it. Shifts are exact powers of two, so
// the final value is bit-identical; staleness only moves the window center
// by <= ~21 bits, covered by recentering at 2^80 (overflow headroom >= 47
// bits, FTZ window >= 128 bits).
// Chunk probs are converted to float in registers at chunk start.
// Mean fused: fixed-point (x 2^32) integer atomic (bit-deterministic).
// ---------------------------------------------------------------------------
#define NWARP 2   // warps (batch elements) per block
__global__ void __launch_bounds__(64) ctc_forward(const int* __restrict__ y_true,
                                                  float* __restrict__ out) {
    __shared__ __align__(16) __half ring[NWARP][NCH][CHUNK * PKW];  // 13.3 KB

    const int wib = threadIdx.x >> 5;
    const int b   = blockIdx.x * NWARP + wib;
    const int l   = threadIdx.x & 31;

    // skip-transition predicates
    int lab0 = 0, lab1 = 0;
    if (l < 24) {
        int2 lp = *(const int2*)(y_true + b * L_DIM + 2 * l);
        lab0 = lp.x; lab1 = lp.y;
    }
    int prevlab1 = __shfl_up_sync(0xFFFFFFFFu, lab1, 1);
    const float skip1 = (l >= 1 && l < 24 && lab0 != prevlab1) ? 1.0f : 0.0f;
    const float skip3 = (l < 24 && lab1 != lab0) ? 1.0f : 0.0f;
    // inactive lanes read probs from the zero pad -> their alphas stay 0
    const int off2 = (l < 24) ? 2 * l : 50;

    const __half* src = g_pk + (size_t)b * T_DIM * PKW;

    // issue one chunk copy: 104 x 16B cp.async, one commit_group
    #define ISSUE(c_)                                                          \
    {                                                                          \
        const __half* gsrc = src + (size_t)(c_) * (CHUNK * PKW);               \
        __half* sdst = &ring[wib][(c_) & (NCH - 1)][0];                        \
        for (int i = l; i < (CHUNK * PKW) / 8; i += 32) {                      \
            unsigned sa = (unsigned)__cvta_generic_to_shared(sdst + 8 * i);    \
            asm volatile("cp.async.ca.shared.global [%0], [%1], 16;"           \
                         :: "r"(sa), "l"(gsrc + 8 * i));                       \
        }                                                                      \
        asm volatile("cp.async.commit_group;" ::: "memory");                   \
    }

    // prologue: chunks 0..NCH-2 in flight
    ISSUE(0); ISSUE(1); ISSUE(2);

    float a0 = 0.0f, a1 = 0.0f, a2 = 0.0f, a3 = 0.0f;
    int acc_k = 0;   // total power-of-2 shift applied
    int pend  = 0;   // shift computed at previous boundary, applied at next

    #define STEP(j, p01f, pb)                                                  \
    {                                                                          \
        float sh3 = __shfl_up_sync(0xFFFFFFFFu, a3, 1);                        \
        if (l == 0) sh3 = 0.0f;                                                \
        float n0 = (a0 + sh3) * (pb);                                          \
        float n1 = fmaf(skip1, sh3, a0 + a1) * (p01f).x;                       \
        float n2 = (a1 + a2) * (pb);                                           \
        float n3 = fmaf(skip3, a1, a2 + a3) * (p01f).y;                        \
        a0 = n0; a1 = n1; a2 = n2; a3 = n3;                                    \
        if (((j) & 3) == 3) {                                                  \
            /* apply the shift computed 4 steps ago (exact power of 2) */      \
            float scale = __int_as_float((127 + pend) << 23);                  \
            a0 *= scale; a1 *= scale; a2 *= scale; a3 *= scale;                \
            acc_k += pend;                                                     \
            /* issue REDUX now; its result gates nothing for 4 steps */        \
            float v = fmaxf(fmaxf(a0, a1), fmaxf(a2, a3));                     \
            unsigned mb = __reduce_max_sync(0xFFFFFFFFu, __float_as_uint(v));  \
            int sh_ = (127 + RECENTER) - (int)(mb >> 23);                      \
            if (sh_ >  126) sh_ =  126;                                        \
            if (sh_ < -126) sh_ = -126;                                        \
            pend = sh_;                                                        \
        }                                                                      \
    }

    for (int c = 0; c < NCHUNKS; c++) {
        // wait until chunk c's group has completed (groups retire in order)
        int n = NCHUNKS - 1 - c; if (n > NCH - 2) n = NCH - 2;
        if      (n == 2) asm volatile("cp.async.wait_group 2;" ::: "memory");
        else if (n == 1) asm volatile("cp.async.wait_group 1;" ::: "memory");
        else             asm volatile("cp.async.wait_group 0;" ::: "memory");
        __syncwarp();

        // preload + convert the whole chunk's probs (all off the serial chain)
        const __half* pk = &ring[wib][c & (NCH - 1)][0];
        float2 pf[CHUNK];
        float  pbf[CHUNK];
        #pragma unroll
        for (int j = 0; j < CHUNK; j++) {
            pf[j]  = __half22float2(*(const __half2*)(pk + j * PKW + off2));
            pbf[j] = __half2float(pk[j * PKW + 48]);
        }
        __syncwarp();
        // refill the slot consumed NCH-1 chunks from now (never the one read)
        if (c + NCH - 1 < NCHUNKS) ISSUE(c + NCH - 1);

        #pragma unroll
        for (int j = 0; j < CHUNK; j++) {
            if (c == 0 && j == 0) {   // t = 0 init: states 0,1 on lane 0
                if (l == 0) { a0 = pbf[0]; a1 = pf[0].x; }
                continue;
            }
            STEP(j, pf[j], pbf[j]);
        }
    }
    #undef STEP
    #undef ISSUE

    // terminal states: s=95 (lane 23, a3) and s=96 (lane 24, a0)
    float v95 = __shfl_sync(0xFFFFFFFFu, a3, 23);
    float v96 = __shfl_sync(0xFFFFFFFFu, a0, 24);
    if (l == 0) {
        // stored = true * 2^{acc_k + 5*512}  (512 prob factors incl. t=0 init)
        double kk = (double)acc_k + (double)(PSCALE_LOG2 * T_DIM);
        double loss = -log((double)(v95 + v96)) + kk * 0.6931471805599453094;
        // deterministic fused mean: fixed-point (2^32) integer accumulate
        unsigned long long fx = (unsigned long long)(loss * 4294967296.0 + 0.5);
        atomicAdd(&g_acc, fx);
        __threadfence();
        int done = atomicAdd(&g_cnt, 1);
        if (done == B_DIM - 1) {
            g_cnt = 0;   // self-reset for next replay
            unsigned long long tot = atomicAdd(&g_acc, 0ull);
            out[0] = (float)((double)tot * (1.0 / 4294967296.0 / (double)B_DIM));
        }
    }
}

extern "C" void kernel_launch(void* const* d_in, const int* in_sizes, int n_in,
                              void* d_out, int out_size) {
    const int*   y_true;
    const float* y_pred;
    if (in_sizes[0] == B_DIM * L_DIM) {
        y_true = (const int*)d_in[0];
        y_pred = (const float*)d_in[1];
    } else {
        y_true = (const int*)d_in[1];
        y_pred = (const float*)d_in[0];
    }

    // G: fused logsumexp + gather + normalize (fp16 out), smem-staged gathers.
    gather_kernel<<<(T_DIM * B_DIM / 4) / 8, 256>>>(y_pred, y_true);
    // B: forward recursion + fused deterministic mean -> d_out
    ctc_forward<<<B_DIM / NWARP, 64>>>(y_true, (float*)d_out);
}